// round 16
// baseline (speedup 1.0000x reference)
#include <cuda_runtime.h>
#include <cuda_fp16.h>
#include <math.h>
#include <stdint.h>

// Problem dims
#define MTOK   4096      // B*S
#define DMODEL 2048
#define NHEAD  16
#define HDIM   128
#define FFDIM  8192
#define SEQ    2048
#define NQKV   2304      // 2048 + 128 + 128

// ---------------- scratch (device globals: allocation-free) ----------------
__device__ __half g_hh [MTOK * DMODEL];          // LN output (half)
__device__ __half g_qh [MTOK * DMODEL];          // Q half (pre-scaled)
__device__ __half g_kh [MTOK * HDIM];            // K half
__device__ __half g_vh [MTOK * HDIM];            // V half
__device__ __half g_oh [MTOK * DMODEL];          // attn O (half)
__device__ float  g_x1 [MTOK * DMODEL];          // x + attn_out
__device__ __half g_ffh[(size_t)MTOK * FFDIM];   // FF1 output (half)
// half weights in ORIGINAL [K,N] layout (no transpose)
__device__ __half g_wqkv[(size_t)DMODEL * NQKV]; // [K=2048][2304] = [wq|wk|wv]
__device__ float  g_bqkv[NQKV];
__device__ __half g_wo[DMODEL * DMODEL];
__device__ __half g_w1[(size_t)DMODEL * FFDIM];
__device__ __half g_w2[(size_t)FFDIM * DMODEL];

// ---------------- helpers ----------------
__device__ __forceinline__ float gelu_exact(float x) {
    return 0.5f * x * (1.0f + erff(x * 0.70710678118654752f));
}
__device__ __forceinline__ float ex2(float x) {
    float y; asm("ex2.approx.f32 %0, %1;" : "=f"(y) : "f"(x)); return y;
}
__device__ __forceinline__ void cp16(uint32_t saddr, const void* g) {
    asm volatile("cp.async.cg.shared.global [%0], [%1], 16;" :: "r"(saddr), "l"(g));
}
#define CP_COMMIT() asm volatile("cp.async.commit_group;\n")
#define CP_WAIT(n)  asm volatile("cp.async.wait_group %0;\n" :: "n"(n))

__device__ __forceinline__ void mma_f16(float* c, const uint32_t* a, const uint32_t* b) {
    asm volatile(
        "mma.sync.aligned.m16n8k16.row.col.f32.f16.f16.f32 "
        "{%0,%1,%2,%3}, {%4,%5,%6,%7}, {%8,%9}, {%0,%1,%2,%3};\n"
        : "+f"(c[0]), "+f"(c[1]), "+f"(c[2]), "+f"(c[3])
        : "r"(a[0]), "r"(a[1]), "r"(a[2]), "r"(a[3]), "r"(b[0]), "r"(b[1]));
}
#define LDSM4(r0, r1, r2, r3, addr) \
    asm volatile("ldmatrix.sync.aligned.m8n8.x4.shared.b16 {%0,%1,%2,%3}, [%4];" \
        : "=r"(r0), "=r"(r1), "=r"(r2), "=r"(r3) : "r"(addr))
#define LDSM4T(r0, r1, r2, r3, addr) \
    asm volatile("ldmatrix.sync.aligned.m8n8.x4.trans.shared.b16 {%0,%1,%2,%3}, [%4];" \
        : "=r"(r0), "=r"(r1), "=r"(r2), "=r"(r3) : "r"(addr))

__device__ __forceinline__ uint32_t packh2(float x, float y) {
    __half2 t = __floats2half2_rn(x, y);
    return *(uint32_t*)&t;
}
__device__ __forceinline__ uint2 cvt4(float4 v) {
    union { uint2 u; __half2 h[2]; } p;
    p.h[0] = __floats2half2_rn(v.x, v.y);
    p.h[1] = __floats2half2_rn(v.z, v.w);
    return p.u;
}

// ---------------- LN body ----------------
__device__ __forceinline__ void ln_body(
    int row, int tid, const float* __restrict__ x, const float* __restrict__ sc,
    const float* __restrict__ bi, __half* __restrict__ out)
{
    const float4* xr = (const float4*)(x + (size_t)row * DMODEL);
    float4 a = xr[tid];
    float4 b = xr[tid + 256];
    float s  = a.x + a.y + a.z + a.w + b.x + b.y + b.z + b.w;
    float ss = a.x*a.x + a.y*a.y + a.z*a.z + a.w*a.w
             + b.x*b.x + b.y*b.y + b.z*b.z + b.w*b.w;
    __shared__ float rs[8], rss[8];
    #pragma unroll
    for (int off = 16; off; off >>= 1) {
        s  += __shfl_xor_sync(0xffffffffu, s,  off);
        ss += __shfl_xor_sync(0xffffffffu, ss, off);
    }
    if ((tid & 31) == 0) { rs[tid >> 5] = s; rss[tid >> 5] = ss; }
    __syncthreads();
    float tot = 0.f, tot2 = 0.f;
    #pragma unroll
    for (int i = 0; i < 8; i++) { tot += rs[i]; tot2 += rss[i]; }
    float mean = tot * (1.0f / DMODEL);
    float var  = tot2 * (1.0f / DMODEL) - mean * mean;
    float rstd = rsqrtf(var + 1e-5f);

    const float4* s4 = (const float4*)sc;
    const float4* b4 = (const float4*)bi;
    float4 sc0 = s4[tid], bi0 = b4[tid], sc1 = s4[tid + 256], bi1 = b4[tid + 256];
    __half* orow = out + (size_t)row * DMODEL;
    float4 r0 = make_float4((a.x - mean) * rstd * sc0.x + bi0.x,
                            (a.y - mean) * rstd * sc0.y + bi0.y,
                            (a.z - mean) * rstd * sc0.z + bi0.z,
                            (a.w - mean) * rstd * sc0.w + bi0.w);
    float4 r1 = make_float4((b.x - mean) * rstd * sc1.x + bi1.x,
                            (b.y - mean) * rstd * sc1.y + bi1.y,
                            (b.z - mean) * rstd * sc1.z + bi1.z,
                            (b.w - mean) * rstd * sc1.w + bi1.w);
    *(uint2*)&orow[tid * 4]         = cvt4(r0);
    *(uint2*)&orow[(tid + 256) * 4] = cvt4(r1);
}

__global__ __launch_bounds__(256) void ln_kernel(
    const float* __restrict__ x, const float* __restrict__ sc,
    const float* __restrict__ bi, __half* __restrict__ out)
{
    ln_body(blockIdx.x, threadIdx.x, x, sc, bi, out);
}

// ---------------- merged prep: weight cvt + bias + LN1 ------
__global__ __launch_bounds__(256) void prep_all(
    const float* __restrict__ wq, const float* __restrict__ wk,
    const float* __restrict__ wv, const float* __restrict__ wo,
    const float* __restrict__ w1, const float* __restrict__ w2,
    const float* __restrict__ qb, const float* __restrict__ kb,
    const float* __restrict__ vb,
    const float* __restrict__ x, const float* __restrict__ ln1_s,
    const float* __restrict__ ln1_b,
    __half* __restrict__ cwqkv, __half* __restrict__ cwo,
    __half* __restrict__ cw1, __half* __restrict__ cw2,
    float* __restrict__ bqkv, __half* __restrict__ hh)
{
    int bid = blockIdx.x, tid = threadIdx.x;
    if (bid < 4096) {           // wq -> cwqkv cols [0,2048)
        int idx = bid * 1024 + tid * 4;
        float4 v = *(const float4*)&wq[idx];
        int k = idx >> 11, n = idx & 2047;
        *(uint2*)&cwqkv[(size_t)k * NQKV + n] = cvt4(v);
    } else if (bid < 4352) {    // wk -> cols [2048,2176)
        int idx = (bid - 4096) * 1024 + tid * 4;
        float4 v = *(const float4*)&wk[idx];
        int k = idx >> 7, n = idx & 127;
        *(uint2*)&cwqkv[(size_t)k * NQKV + 2048 + n] = cvt4(v);
    } else if (bid < 4608) {    // wv -> cols [2176,2304)
        int idx = (bid - 4352) * 1024 + tid * 4;
        float4 v = *(const float4*)&wv[idx];
        int k = idx >> 7, n = idx & 127;
        *(uint2*)&cwqkv[(size_t)k * NQKV + 2176 + n] = cvt4(v);
    } else if (bid < 8704) {    // wo
        int idx = (bid - 4608) * 1024 + tid * 4;
        *(uint2*)&cwo[idx] = cvt4(*(const float4*)&wo[idx]);
    } else if (bid < 25088) {   // w1
        int idx = (bid - 8704) * 1024 + tid * 4;
        *(uint2*)&cw1[idx] = cvt4(*(const float4*)&w1[idx]);
    } else if (bid < 41472) {   // w2
        int idx = (bid - 25088) * 1024 + tid * 4;
        *(uint2*)&cw2[idx] = cvt4(*(const float4*)&w2[idx]);
    } else if (bid < 41481) {   // bias concat
        int i = (bid - 41472) * 256 + tid;
        if (i < DMODEL) bqkv[i] = qb[i];
        else if (i < DMODEL + HDIM) bqkv[i] = kb[i - DMODEL];
        else if (i < NQKV) bqkv[i] = vb[i - DMODEL - HDIM];
    } else {                    // LN1
        ln_body(bid - 41481, tid, x, ln1_s, ln1_b, hh);
    }
}

// ---------------- shared GEMM tiling constants ----------------
// 512 threads, 16 warps in 4x4: warp tile 32 x 64. CTA tile 128 x 256.
#define GBN  256
#define GKS  32
#define GST  4        // pipeline stages
#define GSA  40       // A smem stride (halves)
#define GSB  264      // B smem stride (halves): [32 k][256+8 n]
#define GASZ (128 * GSA)
#define GBSZ (32 * GSB)
#define GSTSZ (GASZ + GBSZ)
#define SMEM_H256 (GST * GSTSZ * 2)   // 108544 bytes

// 4-stage mainloop (512 threads); B via ldmatrix.trans from [k][n] layout
#define GEMM_MAINLOOP()                                                        \
    auto loadStage = [&](int slot, int k0) {                                   \
        uint32_t abase = sbase + (uint32_t)(slot * GSTSZ) * 2;                 \
        uint32_t bbase = abase + (uint32_t)GASZ * 2;                           \
        {                                                                      \
            int m = tid >> 2, kc = (tid & 3) << 3;                             \
            cp16(abase + (uint32_t)(m * GSA + kc) * 2,                         \
                 Arow + (size_t)m * K + k0 + kc);                              \
        }                                                                      \
        _Pragma("unroll")                                                      \
        for (int i = 0; i < 2; i++) {                                          \
            int ch = tid + i * 512;                                            \
            int kr = ch >> 5, nc = (ch & 31) << 3;                             \
            cp16(bbase + (uint32_t)(kr * GSB + nc) * 2,                        \
                 Brow + (size_t)(k0 + kr) * N + nc);                           \
        }                                                                      \
    };                                                                         \
    uint32_t aoff = ((uint32_t)((wm + (lane & 15)) * GSA + (lane >> 4) * 8)) * 2; \
    uint32_t boff = ((uint32_t)GASZ +                                          \
        (uint32_t)(((lane & 7) + ((lane >> 3) & 1) * 8) * GSB +                \
                   wn + (lane >> 4) * 8)) * 2;                                 \
    loadStage(0, 0); CP_COMMIT();                                              \
    loadStage(1, GKS); CP_COMMIT();                                            \
    loadStage(2, 2 * GKS); CP_COMMIT();                                        \
    int T = K / GKS;                                                           \
    for (int t = 0; t < T; t++) {                                              \
        CP_WAIT(2);                                                            \
        __syncthreads();                                                       \
        if (t + 3 < T) { loadStage((t + 3) & 3, (t + 3) * GKS); }              \
        CP_COMMIT();                                                           \
        uint32_t aa = sbase + (uint32_t)((t & 3) * GSTSZ) * 2 + aoff;          \
        uint32_t bb = sbase + (uint32_t)((t & 3) * GSTSZ) * 2 + boff;          \
        _Pragma("unroll")                                                      \
        for (int kk = 0; kk < GKS; kk += 16) {                                 \
            uint32_t af[2][4];                                                 \
            _Pragma("unroll")                                                  \
            for (int mi = 0; mi < 2; mi++)                                     \
                LDSM4(af[mi][0], af[mi][1], af[mi][2], af[mi][3],              \
                      aa + (uint32_t)(kk * 2) + (uint32_t)(mi * 16 * GSA * 2));\
            uint32_t bf[8][2];                                                 \
            _Pragma("unroll")                                                  \
            for (int np = 0; np < 4; np++)                                     \
                LDSM4T(bf[2*np][0], bf[2*np][1], bf[2*np+1][0], bf[2*np+1][1], \
                       bb + (uint32_t)(kk * GSB * 2) + (uint32_t)(np * 16 * 2)); \
            _Pragma("unroll")                                                  \
            for (int mi = 0; mi < 2; mi++)                                     \
                _Pragma("unroll")                                              \
                for (int ni = 0; ni < 8; ni++)                                 \
                    mma_f16(acc[mi][ni], af[mi], bf[ni]);                      \
        }                                                                      \
    }

// ---------------- FP16 GEMM (generic epilogues, 512 threads) ----------------
// EPI: 1 = +bias+residual (float out), 2 = +bias -> GELU (half out)
template<int EPI>
__global__ __launch_bounds__(512) void hgemm(
    const __half* __restrict__ A, const __half* __restrict__ Bt,
    const float* __restrict__ bias, const float* __restrict__ res,
    void* __restrict__ Cv, int M, int N, int K)
{
    extern __shared__ __half smem[];
    uint32_t sbase = (uint32_t)__cvta_generic_to_shared(smem);
    int tid = threadIdx.x, lane = tid & 31, w = tid >> 5;
    int wm = (w >> 2) * 32, wn = (w & 3) * 64;
    int r = lane >> 2, cl = lane & 3;
    int bm = blockIdx.y * 128, bn = blockIdx.x * GBN;

    float acc[2][8][4];
    #pragma unroll
    for (int mi = 0; mi < 2; mi++)
        #pragma unroll
        for (int ni = 0; ni < 8; ni++)
            #pragma unroll
            for (int j = 0; j < 4; j++) acc[mi][ni][j] = 0.f;

    const __half* Arow = A + (size_t)bm * K;
    const __half* Brow = Bt + bn;
    GEMM_MAINLOOP();

    #pragma unroll
    for (int mi = 0; mi < 2; mi++) {
        #pragma unroll
        for (int ni = 0; ni < 8; ni++) {
            int row0 = bm + wm + mi * 16 + r;
            int col  = bn + wn + ni * 8 + cl * 2;
            float2 bv = *(const float2*)&bias[col];
            #pragma unroll
            for (int hh = 0; hh < 2; hh++) {
                int row = row0 + hh * 8;
                float v0 = acc[mi][ni][hh * 2 + 0] + bv.x;
                float v1 = acc[mi][ni][hh * 2 + 1] + bv.y;
                if (EPI == 1) {
                    float2 rv = *(const float2*)&res[(size_t)row * N + col];
                    float* Cf = (float*)Cv;
                    *(float2*)&Cf[(size_t)row * N + col] =
                        make_float2(v0 + rv.x, v1 + rv.y);
                } else {
                    __half* Ch = (__half*)Cv;
                    *(__half2*)&Ch[(size_t)row * N + col] =
                        __floats2half2_rn(gelu_exact(v0), gelu_exact(v1));
                }
            }
        }
    }
}

// ---------------- Fused QKV GEMM (512 threads, routing epilogue) ------------
__global__ __launch_bounds__(512) void hgemm_qkv(
    const __half* __restrict__ A, const __half* __restrict__ Bt,
    const float* __restrict__ bias,
    __half* __restrict__ qo, __half* __restrict__ ko, __half* __restrict__ vo,
    int K, float qscale)
{
    extern __shared__ __half smem[];
    uint32_t sbase = (uint32_t)__cvta_generic_to_shared(smem);
    int tid = threadIdx.x, lane = tid & 31, w = tid >> 5;
    int wm = (w >> 2) * 32, wn = (w & 3) * 64;
    int r = lane >> 2, cl = lane & 3;
    int bm = blockIdx.y * 128, bn = blockIdx.x * GBN;
    const int N = NQKV;

    float acc[2][8][4];
    #pragma unroll
    for (int mi = 0; mi < 2; mi++)
        #pragma unroll
        for (int ni = 0; ni < 8; ni++)
            #pragma unroll
            for (int j = 0; j < 4; j++) acc[mi][ni][j] = 0.f;

    const __half* Arow = A + (size_t)bm * K;
    const __half* Brow = Bt + bn;
    GEMM_MAINLOOP();

    #pragma unroll
    for (int mi = 0; mi < 2; mi++) {
        #pragma unroll
        for (int ni = 0; ni < 8; ni++) {
            int row0 = bm + wm + mi * 16 + r;
            int col  = bn + wn + ni * 8 + cl * 2;
            float2 bv = *(const float2*)&bias[col];
            #pragma unroll
            for (int hh = 0; hh < 2; hh++) {
                int row = row0 + hh * 8;
                float v0 = acc[mi][ni][hh * 2 + 0] + bv.x;
                float v1 = acc[mi][ni][hh * 2 + 1] + bv.y;
                if (col < DMODEL) {
                    *(__half2*)&qo[(size_t)row * DMODEL + col] =
                        __floats2half2_rn(v0 * qscale, v1 * qscale);
                } else if (col < DMODEL + HDIM) {
                    *(__half2*)&ko[(size_t)row * HDIM + (col - DMODEL)] =
                        __floats2half2_rn(v0, v1);
                } else {
                    *(__half2*)&vo[(size_t)row * HDIM + (col - DMODEL - HDIM)] =
                        __floats2half2_rn(v0, v1);
                }
            }
        }
    }
}

// ---------------- FP16 flash attention (BQ=128, BK=128, no V transpose) -----
#define SQ  136
#define FA_SMEM (5 * 128 * SQ * 2)   // Q + 2xK + 2xV = 174080 bytes

__global__ __launch_bounds__(256) void fattn(
    const __half* __restrict__ q, const __half* __restrict__ k,
    const __half* __restrict__ v, __half* __restrict__ o)
{
    extern __shared__ __half sm2[];
    uint32_t qb  = (uint32_t)__cvta_generic_to_shared(sm2);
    uint32_t kbb = qb + 128 * SQ * 2;        // [2][128 s][SQ d]
    uint32_t vbb = kbb + 2 * 128 * SQ * 2;   // [2][128 s][SQ d]

    int tid = threadIdx.x, lane = tid & 31, w = tid >> 5;
    int qt = (int)gridDim.x - 1 - (int)blockIdx.x;   // longest first
    int bh = blockIdx.y, b = bh >> 4, h = bh & 15;
    int qs0 = qt * 128;
    int r = lane >> 2, cl = lane & 3;
    int m0 = w * 16;

    const __half* qp = q + ((size_t)(b * SEQ + qs0) * NHEAD + h) * HDIM;
    #pragma unroll
    for (int i = 0; i < 8; i++) {
        int ch = tid + i * 256; int rr = ch >> 4, c = (ch & 15) * 8;
        cp16(qb + (uint32_t)(rr * SQ + c) * 2, qp + (size_t)rr * (NHEAD * HDIM) + c);
    }

    auto loadKV = [&](int st, int kt) {
        int ks0 = kt * 128;
        const __half* kp = k + ((size_t)b * SEQ + ks0) * HDIM;
        uint32_t kbs = kbb + (uint32_t)st * 128 * SQ * 2;
        #pragma unroll
        for (int i = 0; i < 8; i++) {
            int ch = tid + i * 256; int rr = ch >> 4, c = (ch & 15) * 8;
            cp16(kbs + (uint32_t)(rr * SQ + c) * 2, kp + (size_t)rr * HDIM + c);
        }
        const __half* vp = v + ((size_t)b * SEQ + ks0) * HDIM;
        uint32_t vbs = vbb + (uint32_t)st * 128 * SQ * 2;
        #pragma unroll
        for (int i = 0; i < 8; i++) {
            int ch = tid + i * 256; int rr = ch >> 4, c = (ch & 15) * 8;
            cp16(vbs + (uint32_t)(rr * SQ + c) * 2, vp + (size_t)rr * HDIM + c);
        }
    };

    loadKV(0, 0);
    CP_COMMIT();

    uint32_t qaddr = qb + (uint32_t)((m0 + (lane & 15)) * SQ + (lane >> 4) * 8) * 2;
    uint32_t koff  = (uint32_t)(((lane >> 4) * 8 + (lane & 7)) * SQ +
                                ((lane >> 3) & 1) * 8) * 2;
    uint32_t voff  = (uint32_t)(((lane & 7) + ((lane >> 3) & 1) * 8) * SQ +
                                (lane >> 4) * 8) * 2;

    float m_0 = -1e30f, m_1 = -1e30f, l_0 = 0.f, l_1 = 0.f;
    float oacc[16][4];
    #pragma unroll
    for (int di = 0; di < 16; di++)
        #pragma unroll
        for (int j = 0; j < 4; j++) oacc[di][j] = 0.f;

    int nkt = qt + 1;
    for (int kt = 0; kt < nkt; kt++) {
        CP_WAIT(0);
        __syncthreads();
        if (kt + 1 < nkt) { loadKV((kt + 1) & 1, kt + 1); CP_COMMIT(); }
        uint32_t ka = kbb + (uint32_t)((kt & 1) * 128 * SQ) * 2 + koff;
        uint32_t va = vbb + (uint32_t)((kt & 1) * 128 * SQ) * 2 + voff;

        // S = Q K^T  (16 x 128 per warp)
        float sacc[16][4];
        #pragma unroll
        for (int ni = 0; ni < 16; ni++)
            #pragma unroll
            for (int j = 0; j < 4; j++) sacc[ni][j] = 0.f;

        #pragma unroll
        for (int kk = 0; kk < 128; kk += 16) {
            uint32_t af[4];
            LDSM4(af[0], af[1], af[2], af[3], qaddr + (uint32_t)(kk * 2));
            uint32_t bf[16][2];
            #pragma unroll
            for (int np = 0; np < 8; np++)
                LDSM4(bf[2*np][0], bf[2*np][1], bf[2*np+1][0], bf[2*np+1][1],
                      ka + (uint32_t)(kk * 2) + (uint32_t)(np * 16 * SQ * 2));
            #pragma unroll
            for (int ni = 0; ni < 16; ni++)
                mma_f16(sacc[ni], af, bf[ni]);
        }

        // causal mask: only the diagonal tile needs it
        if (kt == qt) {
            int ks0 = kt * 128;
            int row0 = qs0 + m0 + r, row1 = row0 + 8;
            #pragma unroll
            for (int ni = 0; ni < 16; ni++) {
                int c0 = ks0 + ni * 8 + cl * 2, c1 = c0 + 1;
                if (c0 > row0) sacc[ni][0] = -1e30f;
                if (c1 > row0) sacc[ni][1] = -1e30f;
                if (c0 > row1) sacc[ni][2] = -1e30f;
                if (c1 > row1) sacc[ni][3] = -1e30f;
            }
        }

        // online softmax (base 2)
        float mx0 = -1e30f, mx1 = -1e30f;
        #pragma unroll
        for (int ni = 0; ni < 16; ni++) {
            mx0 = fmaxf(mx0, fmaxf(sacc[ni][0], sacc[ni][1]));
            mx1 = fmaxf(mx1, fmaxf(sacc[ni][2], sacc[ni][3]));
        }
        mx0 = fmaxf(mx0, __shfl_xor_sync(0xffffffffu, mx0, 1));
        mx0 = fmaxf(mx0, __shfl_xor_sync(0xffffffffu, mx0, 2));
        mx1 = fmaxf(mx1, __shfl_xor_sync(0xffffffffu, mx1, 1));
        mx1 = fmaxf(mx1, __shfl_xor_sync(0xffffffffu, mx1, 2));
        float mn0 = fmaxf(m_0, mx0), mn1 = fmaxf(m_1, mx1);
        float a0 = ex2(m_0 - mn0), a1 = ex2(m_1 - mn1);
        float s0 = 0.f, s1 = 0.f;
        #pragma unroll
        for (int ni = 0; ni < 16; ni++) {
            sacc[ni][0] = ex2(sacc[ni][0] - mn0);
            sacc[ni][1] = ex2(sacc[ni][1] - mn0);
            sacc[ni][2] = ex2(sacc[ni][2] - mn1);
            sacc[ni][3] = ex2(sacc[ni][3] - mn1);
            s0 += sacc[ni][0] + sacc[ni][1];
            s1 += sacc[ni][2] + sacc[ni][3];
        }
        s0 += __shfl_xor_sync(0xffffffffu, s0, 1);
        s0 += __shfl_xor_sync(0xffffffffu, s0, 2);
        s1 += __shfl_xor_sync(0xffffffffu, s1, 1);
        s1 += __shfl_xor_sync(0xffffffffu, s1, 2);
        l_0 = l_0 * a0 + s0; l_1 = l_1 * a1 + s1;
        m_0 = mn0; m_1 = mn1;
        #pragma unroll
        for (int di = 0; di < 16; di++) {
            oacc[di][0] *= a0; oacc[di][1] *= a0;
            oacc[di][2] *= a1; oacc[di][3] *= a1;
        }

        // P fragments (registers -> A-frag)
        uint32_t pa[8][4];
        #pragma unroll
        for (int j = 0; j < 8; j++) {
            pa[j][0] = packh2(sacc[2*j  ][0], sacc[2*j  ][1]);
            pa[j][1] = packh2(sacc[2*j  ][2], sacc[2*j  ][3]);
            pa[j][2] = packh2(sacc[2*j+1][0], sacc[2*j+1][1]);
            pa[j][3] = packh2(sacc[2*j+1][2], sacc[2*j+1][3]);
        }

        // O += P V   (V [s][d] via ldmatrix.trans)
        #pragma unroll
        for (int j = 0; j < 8; j++) {
            #pragma unroll
            for (int dp = 0; dp < 8; dp++) {
                uint32_t bf[4];
                LDSM4T(bf[0], bf[1], bf[2], bf[3],
                       va + (uint32_t)(j * 16 * SQ * 2) + (uint32_t)(dp * 16 * 2));
                mma_f16(oacc[2*dp    ], pa[j], bf    );
                mma_f16(oacc[2*dp + 1], pa[j], bf + 2);
            }
        }
    }

    // epilogue
    float i0 = 1.f / l_0, i1 = 1.f / l_1;
    __half* op = o + ((size_t)(b * SEQ + qs0 + m0) * NHEAD + h) * HDIM;
    #pragma unroll
    for (int di = 0; di < 16; di++) {
        int c = di * 8 + cl * 2;
        *(__half2*)&op[(size_t)r * (NHEAD * HDIM) + c] =
            __floats2half2_rn(oacc[di][0] * i0, oacc[di][1] * i0);
        *(__half2*)&op[(size_t)(r + 8) * (NHEAD * HDIM) + c] =
            __floats2half2_rn(oacc[di][2] * i1, oacc[di][3] * i1);
    }
}

// ---------------- launch ----------------
extern "C" void kernel_launch(void* const* d_in, const int* in_sizes, int n_in,
                              void* d_out, int out_size)
{
    const float* x     = (const float*)d_in[0];
    const float* wq    = (const float*)d_in[2];
    const float* wq_b  = (const float*)d_in[3];
    const float* wk    = (const float*)d_in[4];
    const float* wk_b  = (const float*)d_in[5];
    const float* wv    = (const float*)d_in[6];
    const float* wv_b  = (const float*)d_in[7];
    const float* wo    = (const float*)d_in[8];
    const float* wo_b  = (const float*)d_in[9];
    const float* w1    = (const float*)d_in[10];
    const float* w1_b  = (const float*)d_in[11];
    const float* w2    = (const float*)d_in[12];
    const float* w2_b  = (const float*)d_in[13];
    const float* ln1_s = (const float*)d_in[14];
    const float* ln1_b = (const float*)d_in[15];
    const float* ln2_s = (const float*)d_in[16];
    const float* ln2_b = (const float*)d_in[17];
    float* out = (float*)d_out;

    __half *hh, *qh, *kh, *vh, *oh, *ffh;
    __half *cwqkv, *cwo, *cw1, *cw2;
    float  *x1, *bqkv;
    cudaGetSymbolAddress((void**)&hh,    g_hh);
    cudaGetSymbolAddress((void**)&qh,    g_qh);
    cudaGetSymbolAddress((void**)&kh,    g_kh);
    cudaGetSymbolAddress((void**)&vh,    g_vh);
    cudaGetSymbolAddress((void**)&oh,    g_oh);
    cudaGetSymbolAddress((void**)&x1,    g_x1);
    cudaGetSymbolAddress((void**)&ffh,   g_ffh);
    cudaGetSymbolAddress((void**)&cwqkv, g_wqkv);
    cudaGetSymbolAddress((void**)&bqkv,  g_bqkv);
    cudaGetSymbolAddress((void**)&cwo,   g_wo);
    cudaGetSymbolAddress((void**)&cw1,   g_w1);
    cudaGetSymbolAddress((void**)&cw2,   g_w2);

    cudaFuncSetAttribute(fattn, cudaFuncAttributeMaxDynamicSharedMemorySize, FA_SMEM);
    cudaFuncSetAttribute(hgemm<1>, cudaFuncAttributeMaxDynamicSharedMemorySize, SMEM_H256);
    cudaFuncSetAttribute(hgemm<2>, cudaFuncAttributeMaxDynamicSharedMemorySize, SMEM_H256);
    cudaFuncSetAttribute(hgemm_qkv, cudaFuncAttributeMaxDynamicSharedMemorySize, SMEM_H256);

    // Q pre-scale folds softmax scale AND log2(e) for base-2 softmax
    const float qscale = 0.08838834764831845f * 1.44269504088896340f;

    // 1: all prep (weight cvt + bias concat + LN1) in one launch
    prep_all<<<45577, 256>>>(wq, wk, wv, wo, w1, w2, wq_b, wk_b, wv_b,
                             x, ln1_s, ln1_b, cwqkv, cwo, cw1, cw2, bqkv, hh);
    // 2: fused QKV projection
    hgemm_qkv<<<dim3(NQKV/GBN, MTOK/128), 512, SMEM_H256>>>(
        hh, cwqkv, bqkv, qh, kh, vh, DMODEL, qscale);
    // 3: attention (half out, V untransposed)
    fattn<<<dim3(SEQ/128, 2*NHEAD), 256, FA_SMEM>>>(qh, kh, vh, oh);
    // 4: x1 = x + O @ wo + wo_b  (float out)
    hgemm<1><<<dim3(DMODEL/GBN, MTOK/128), 512, SMEM_H256>>>(
        oh, cwo, wo_b, x, x1, MTOK, DMODEL, DMODEL);
    // 5: h = LN2(x1) (half)
    ln_kernel<<<MTOK, 256>>>(x1, ln2_s, ln2_b, hh);
    // 6: ff = gelu(h @ w1 + w1_b)  (half out)
    hgemm<2><<<dim3(FFDIM/GBN, MTOK/128), 512, SMEM_H256>>>(
        hh, cw1, w1_b, nullptr, ffh, MTOK, FFDIM, DMODEL);
    // 7: out = x1 + ff @ w2 + w2_b (float out)
    hgemm<1><<<dim3(DMODEL/GBN, MTOK/128), 512, SMEM_H256>>>(
        ffh, cw2, w2_b, x1, out, MTOK, DMODEL, FFDIM);
}

// round 17
// speedup vs baseline: 1.1108x; 1.1108x over previous
#include <cuda_runtime.h>
#include <cuda_fp16.h>
#include <math.h>
#include <stdint.h>

// Problem dims
#define MTOK   4096      // B*S
#define DMODEL 2048
#define NHEAD  16
#define HDIM   128
#define FFDIM  8192
#define SEQ    2048
#define NQKV   2304      // 2048 + 128 + 128

// ---------------- scratch (device globals: allocation-free) ----------------
__device__ __half g_hh [MTOK * DMODEL];          // LN output (half)
__device__ __half g_qh [MTOK * DMODEL];          // Q half (pre-scaled)
__device__ __half g_kh [MTOK * HDIM];            // K half
__device__ __half g_vh [MTOK * HDIM];            // V half
__device__ __half g_oh [MTOK * DMODEL];          // attn O (half)
__device__ float  g_x1 [MTOK * DMODEL];          // x + attn_out
__device__ __half g_ffh[(size_t)MTOK * FFDIM];   // FF1 output (half)
// half weights in ORIGINAL [K,N] layout (no transpose)
__device__ __half g_wqkv[(size_t)DMODEL * NQKV]; // [K=2048][2304] = [wq|wk|wv]
__device__ float  g_bqkv[NQKV];
__device__ __half g_wo[DMODEL * DMODEL];
__device__ __half g_w1[(size_t)DMODEL * FFDIM];
__device__ __half g_w2[(size_t)FFDIM * DMODEL];

// ---------------- helpers ----------------
__device__ __forceinline__ float gelu_exact(float x) {
    return 0.5f * x * (1.0f + erff(x * 0.70710678118654752f));
}
__device__ __forceinline__ float ex2(float x) {
    float y; asm("ex2.approx.f32 %0, %1;" : "=f"(y) : "f"(x)); return y;
}
__device__ __forceinline__ void cp16(uint32_t saddr, const void* g) {
    asm volatile("cp.async.cg.shared.global [%0], [%1], 16;" :: "r"(saddr), "l"(g));
}
#define CP_COMMIT() asm volatile("cp.async.commit_group;\n")
#define CP_WAIT(n)  asm volatile("cp.async.wait_group %0;\n" :: "n"(n))

__device__ __forceinline__ void mma_f16(float* c, const uint32_t* a, const uint32_t* b) {
    asm volatile(
        "mma.sync.aligned.m16n8k16.row.col.f32.f16.f16.f32 "
        "{%0,%1,%2,%3}, {%4,%5,%6,%7}, {%8,%9}, {%0,%1,%2,%3};\n"
        : "+f"(c[0]), "+f"(c[1]), "+f"(c[2]), "+f"(c[3])
        : "r"(a[0]), "r"(a[1]), "r"(a[2]), "r"(a[3]), "r"(b[0]), "r"(b[1]));
}
#define LDSM4(r0, r1, r2, r3, addr) \
    asm volatile("ldmatrix.sync.aligned.m8n8.x4.shared.b16 {%0,%1,%2,%3}, [%4];" \
        : "=r"(r0), "=r"(r1), "=r"(r2), "=r"(r3) : "r"(addr))
#define LDSM4T(r0, r1, r2, r3, addr) \
    asm volatile("ldmatrix.sync.aligned.m8n8.x4.trans.shared.b16 {%0,%1,%2,%3}, [%4];" \
        : "=r"(r0), "=r"(r1), "=r"(r2), "=r"(r3) : "r"(addr))

__device__ __forceinline__ uint32_t packh2(float x, float y) {
    __half2 t = __floats2half2_rn(x, y);
    return *(uint32_t*)&t;
}
__device__ __forceinline__ uint2 cvt4(float4 v) {
    union { uint2 u; __half2 h[2]; } p;
    p.h[0] = __floats2half2_rn(v.x, v.y);
    p.h[1] = __floats2half2_rn(v.z, v.w);
    return p.u;
}

// ---------------- LN body ----------------
__device__ __forceinline__ void ln_body(
    int row, int tid, const float* __restrict__ x, const float* __restrict__ sc,
    const float* __restrict__ bi, __half* __restrict__ out)
{
    const float4* xr = (const float4*)(x + (size_t)row * DMODEL);
    float4 a = xr[tid];
    float4 b = xr[tid + 256];
    float s  = a.x + a.y + a.z + a.w + b.x + b.y + b.z + b.w;
    float ss = a.x*a.x + a.y*a.y + a.z*a.z + a.w*a.w
             + b.x*b.x + b.y*b.y + b.z*b.z + b.w*b.w;
    __shared__ float rs[8], rss[8];
    #pragma unroll
    for (int off = 16; off; off >>= 1) {
        s  += __shfl_xor_sync(0xffffffffu, s,  off);
        ss += __shfl_xor_sync(0xffffffffu, ss, off);
    }
    if ((tid & 31) == 0) { rs[tid >> 5] = s; rss[tid >> 5] = ss; }
    __syncthreads();
    float tot = 0.f, tot2 = 0.f;
    #pragma unroll
    for (int i = 0; i < 8; i++) { tot += rs[i]; tot2 += rss[i]; }
    float mean = tot * (1.0f / DMODEL);
    float var  = tot2 * (1.0f / DMODEL) - mean * mean;
    float rstd = rsqrtf(var + 1e-5f);

    const float4* s4 = (const float4*)sc;
    const float4* b4 = (const float4*)bi;
    float4 sc0 = s4[tid], bi0 = b4[tid], sc1 = s4[tid + 256], bi1 = b4[tid + 256];
    __half* orow = out + (size_t)row * DMODEL;
    float4 r0 = make_float4((a.x - mean) * rstd * sc0.x + bi0.x,
                            (a.y - mean) * rstd * sc0.y + bi0.y,
                            (a.z - mean) * rstd * sc0.z + bi0.z,
                            (a.w - mean) * rstd * sc0.w + bi0.w);
    float4 r1 = make_float4((b.x - mean) * rstd * sc1.x + bi1.x,
                            (b.y - mean) * rstd * sc1.y + bi1.y,
                            (b.z - mean) * rstd * sc1.z + bi1.z,
                            (b.w - mean) * rstd * sc1.w + bi1.w);
    *(uint2*)&orow[tid * 4]         = cvt4(r0);
    *(uint2*)&orow[(tid + 256) * 4] = cvt4(r1);
}

__global__ __launch_bounds__(256) void ln_kernel(
    const float* __restrict__ x, const float* __restrict__ sc,
    const float* __restrict__ bi, __half* __restrict__ out)
{
    ln_body(blockIdx.x, threadIdx.x, x, sc, bi, out);
}

// ---------------- merged prep: weight cvt + bias + LN1 ------
__global__ __launch_bounds__(256) void prep_all(
    const float* __restrict__ wq, const float* __restrict__ wk,
    const float* __restrict__ wv, const float* __restrict__ wo,
    const float* __restrict__ w1, const float* __restrict__ w2,
    const float* __restrict__ qb, const float* __restrict__ kb,
    const float* __restrict__ vb,
    const float* __restrict__ x, const float* __restrict__ ln1_s,
    const float* __restrict__ ln1_b,
    __half* __restrict__ cwqkv, __half* __restrict__ cwo,
    __half* __restrict__ cw1, __half* __restrict__ cw2,
    float* __restrict__ bqkv, __half* __restrict__ hh)
{
    int bid = blockIdx.x, tid = threadIdx.x;
    if (bid < 4096) {           // wq -> cwqkv cols [0,2048)
        int idx = bid * 1024 + tid * 4;
        float4 v = *(const float4*)&wq[idx];
        int k = idx >> 11, n = idx & 2047;
        *(uint2*)&cwqkv[(size_t)k * NQKV + n] = cvt4(v);
    } else if (bid < 4352) {    // wk -> cols [2048,2176)
        int idx = (bid - 4096) * 1024 + tid * 4;
        float4 v = *(const float4*)&wk[idx];
        int k = idx >> 7, n = idx & 127;
        *(uint2*)&cwqkv[(size_t)k * NQKV + 2048 + n] = cvt4(v);
    } else if (bid < 4608) {    // wv -> cols [2176,2304)
        int idx = (bid - 4352) * 1024 + tid * 4;
        float4 v = *(const float4*)&wv[idx];
        int k = idx >> 7, n = idx & 127;
        *(uint2*)&cwqkv[(size_t)k * NQKV + 2176 + n] = cvt4(v);
    } else if (bid < 8704) {    // wo
        int idx = (bid - 4608) * 1024 + tid * 4;
        *(uint2*)&cwo[idx] = cvt4(*(const float4*)&wo[idx]);
    } else if (bid < 25088) {   // w1
        int idx = (bid - 8704) * 1024 + tid * 4;
        *(uint2*)&cw1[idx] = cvt4(*(const float4*)&w1[idx]);
    } else if (bid < 41472) {   // w2
        int idx = (bid - 25088) * 1024 + tid * 4;
        *(uint2*)&cw2[idx] = cvt4(*(const float4*)&w2[idx]);
    } else if (bid < 41481) {   // bias concat
        int i = (bid - 41472) * 256 + tid;
        if (i < DMODEL) bqkv[i] = qb[i];
        else if (i < DMODEL + HDIM) bqkv[i] = kb[i - DMODEL];
        else if (i < NQKV) bqkv[i] = vb[i - DMODEL - HDIM];
    } else {                    // LN1
        ln_body(bid - 41481, tid, x, ln1_s, ln1_b, hh);
    }
}

// ---------------- shared GEMM tiling constants ----------------
// 256 threads, 8 warps in 4x2: warp tile 32 x 64. CTA tile 128 x 128.
// 3-stage pipeline, 56.8 KB smem -> 2 CTAs per SM (antiphase barriers).
#define GBN  128
#define GKS  32
#define GST  3
#define GSA  40       // A smem stride (halves)
#define GSB  136      // B smem stride (halves): [32 k][128+8 n]
#define GASZ (128 * GSA)
#define GBSZ (32 * GSB)
#define GSTSZ (GASZ + GBSZ)
#define SMEM_H (GST * GSTSZ * 2)   // 56832 bytes

// 3-stage mainloop (256 threads); B via ldmatrix.trans from [k][n] layout
#define GEMM_MAINLOOP()                                                        \
    auto loadStage = [&](int slot, int k0) {                                   \
        uint32_t abase = sbase + (uint32_t)(slot * GSTSZ) * 2;                 \
        uint32_t bbase = abase + (uint32_t)GASZ * 2;                           \
        _Pragma("unroll")                                                      \
        for (int i = 0; i < 2; i++) {                                          \
            int ch = tid + i * 256;                                            \
            int m = ch >> 2, kc = (ch & 3) << 3;                               \
            cp16(abase + (uint32_t)(m * GSA + kc) * 2,                         \
                 Arow + (size_t)m * K + k0 + kc);                              \
        }                                                                      \
        _Pragma("unroll")                                                      \
        for (int i = 0; i < 2; i++) {                                          \
            int ch = tid + i * 256;                                            \
            int kr = ch >> 4, nc = (ch & 15) << 3;                             \
            cp16(bbase + (uint32_t)(kr * GSB + nc) * 2,                        \
                 Brow + (size_t)(k0 + kr) * N + nc);                           \
        }                                                                      \
    };                                                                         \
    uint32_t aoff = ((uint32_t)((wm + (lane & 15)) * GSA + (lane >> 4) * 8)) * 2; \
    uint32_t boff = ((uint32_t)GASZ +                                          \
        (uint32_t)(((lane & 7) + ((lane >> 3) & 1) * 8) * GSB +                \
                   wn + (lane >> 4) * 8)) * 2;                                 \
    loadStage(0, 0); CP_COMMIT();                                              \
    loadStage(1, GKS); CP_COMMIT();                                            \
    int T = K / GKS;                                                           \
    for (int t = 0; t < T; t++) {                                              \
        CP_WAIT(1);                                                            \
        __syncthreads();                                                       \
        if (t + 2 < T) { loadStage((t + 2) % GST, (t + 2) * GKS); }            \
        CP_COMMIT();                                                           \
        uint32_t aa = sbase + (uint32_t)((t % GST) * GSTSZ) * 2 + aoff;        \
        uint32_t bb = sbase + (uint32_t)((t % GST) * GSTSZ) * 2 + boff;        \
        _Pragma("unroll")                                                      \
        for (int kk = 0; kk < GKS; kk += 16) {                                 \
            uint32_t af[2][4];                                                 \
            _Pragma("unroll")                                                  \
            for (int mi = 0; mi < 2; mi++)                                     \
                LDSM4(af[mi][0], af[mi][1], af[mi][2], af[mi][3],              \
                      aa + (uint32_t)(kk * 2) + (uint32_t)(mi * 16 * GSA * 2));\
            uint32_t bf[8][2];                                                 \
            _Pragma("unroll")                                                  \
            for (int np = 0; np < 4; np++)                                     \
                LDSM4T(bf[2*np][0], bf[2*np][1], bf[2*np+1][0], bf[2*np+1][1], \
                       bb + (uint32_t)(kk * GSB * 2) + (uint32_t)(np * 16 * 2)); \
            _Pragma("unroll")                                                  \
            for (int mi = 0; mi < 2; mi++)                                     \
                _Pragma("unroll")                                              \
                for (int ni = 0; ni < 8; ni++)                                 \
                    mma_f16(acc[mi][ni], af[mi], bf[ni]);                      \
        }                                                                      \
    }

// ---------------- FP16 GEMM (generic epilogues, 2 CTAs/SM) ----------------
// EPI: 1 = +bias+residual (float out), 2 = +bias -> GELU (half out)
template<int EPI>
__global__ __launch_bounds__(256, 2) void hgemm(
    const __half* __restrict__ A, const __half* __restrict__ Bt,
    const float* __restrict__ bias, const float* __restrict__ res,
    void* __restrict__ Cv, int M, int N, int K)
{
    extern __shared__ __half smem[];
    uint32_t sbase = (uint32_t)__cvta_generic_to_shared(smem);
    int tid = threadIdx.x, lane = tid & 31, w = tid >> 5;
    int wm = (w >> 1) * 32, wn = (w & 1) * 64;
    int r = lane >> 2, cl = lane & 3;
    int bm = blockIdx.y * 128, bn = blockIdx.x * GBN;

    float acc[2][8][4];
    #pragma unroll
    for (int mi = 0; mi < 2; mi++)
        #pragma unroll
        for (int ni = 0; ni < 8; ni++)
            #pragma unroll
            for (int j = 0; j < 4; j++) acc[mi][ni][j] = 0.f;

    const __half* Arow = A + (size_t)bm * K;
    const __half* Brow = Bt + bn;
    GEMM_MAINLOOP();

    #pragma unroll
    for (int mi = 0; mi < 2; mi++) {
        #pragma unroll
        for (int ni = 0; ni < 8; ni++) {
            int row0 = bm + wm + mi * 16 + r;
            int col  = bn + wn + ni * 8 + cl * 2;
            float2 bv = *(const float2*)&bias[col];
            #pragma unroll
            for (int hh = 0; hh < 2; hh++) {
                int row = row0 + hh * 8;
                float v0 = acc[mi][ni][hh * 2 + 0] + bv.x;
                float v1 = acc[mi][ni][hh * 2 + 1] + bv.y;
                if (EPI == 1) {
                    float2 rv = *(const float2*)&res[(size_t)row * N + col];
                    float* Cf = (float*)Cv;
                    *(float2*)&Cf[(size_t)row * N + col] =
                        make_float2(v0 + rv.x, v1 + rv.y);
                } else {
                    __half* Ch = (__half*)Cv;
                    *(__half2*)&Ch[(size_t)row * N + col] =
                        __floats2half2_rn(gelu_exact(v0), gelu_exact(v1));
                }
            }
        }
    }
}

// ---------------- Fused QKV GEMM (routing epilogue, 2 CTAs/SM) --------------
__global__ __launch_bounds__(256, 2) void hgemm_qkv(
    const __half* __restrict__ A, const __half* __restrict__ Bt,
    const float* __restrict__ bias,
    __half* __restrict__ qo, __half* __restrict__ ko, __half* __restrict__ vo,
    int K, float qscale)
{
    extern __shared__ __half smem[];
    uint32_t sbase = (uint32_t)__cvta_generic_to_shared(smem);
    int tid = threadIdx.x, lane = tid & 31, w = tid >> 5;
    int wm = (w >> 1) * 32, wn = (w & 1) * 64;
    int r = lane >> 2, cl = lane & 3;
    int bm = blockIdx.y * 128, bn = blockIdx.x * GBN;
    const int N = NQKV;

    float acc[2][8][4];
    #pragma unroll
    for (int mi = 0; mi < 2; mi++)
        #pragma unroll
        for (int ni = 0; ni < 8; ni++)
            #pragma unroll
            for (int j = 0; j < 4; j++) acc[mi][ni][j] = 0.f;

    const __half* Arow = A + (size_t)bm * K;
    const __half* Brow = Bt + bn;
    GEMM_MAINLOOP();

    #pragma unroll
    for (int mi = 0; mi < 2; mi++) {
        #pragma unroll
        for (int ni = 0; ni < 8; ni++) {
            int row0 = bm + wm + mi * 16 + r;
            int col  = bn + wn + ni * 8 + cl * 2;
            float2 bv = *(const float2*)&bias[col];
            #pragma unroll
            for (int hh = 0; hh < 2; hh++) {
                int row = row0 + hh * 8;
                float v0 = acc[mi][ni][hh * 2 + 0] + bv.x;
                float v1 = acc[mi][ni][hh * 2 + 1] + bv.y;
                if (col < DMODEL) {
                    *(__half2*)&qo[(size_t)row * DMODEL + col] =
                        __floats2half2_rn(v0 * qscale, v1 * qscale);
                } else if (col < DMODEL + HDIM) {
                    *(__half2*)&ko[(size_t)row * HDIM + (col - DMODEL)] =
                        __floats2half2_rn(v0, v1);
                } else {
                    *(__half2*)&vo[(size_t)row * HDIM + (col - DMODEL - HDIM)] =
                        __floats2half2_rn(v0, v1);
                }
            }
        }
    }
}

// ---------------- FP16 flash attention (BQ=128, BK=128, no V transpose) -----
#define SQ  136
#define FA_SMEM (5 * 128 * SQ * 2)   // Q + 2xK + 2xV = 174080 bytes

__global__ __launch_bounds__(256) void fattn(
    const __half* __restrict__ q, const __half* __restrict__ k,
    const __half* __restrict__ v, __half* __restrict__ o)
{
    extern __shared__ __half sm2[];
    uint32_t qb  = (uint32_t)__cvta_generic_to_shared(sm2);
    uint32_t kbb = qb + 128 * SQ * 2;        // [2][128 s][SQ d]
    uint32_t vbb = kbb + 2 * 128 * SQ * 2;   // [2][128 s][SQ d]

    int tid = threadIdx.x, lane = tid & 31, w = tid >> 5;
    int qt = (int)gridDim.x - 1 - (int)blockIdx.x;   // longest first
    int bh = blockIdx.y, b = bh >> 4, h = bh & 15;
    int qs0 = qt * 128;
    int r = lane >> 2, cl = lane & 3;
    int m0 = w * 16;

    const __half* qp = q + ((size_t)(b * SEQ + qs0) * NHEAD + h) * HDIM;
    #pragma unroll
    for (int i = 0; i < 8; i++) {
        int ch = tid + i * 256; int rr = ch >> 4, c = (ch & 15) * 8;
        cp16(qb + (uint32_t)(rr * SQ + c) * 2, qp + (size_t)rr * (NHEAD * HDIM) + c);
    }

    auto loadKV = [&](int st, int kt) {
        int ks0 = kt * 128;
        const __half* kp = k + ((size_t)b * SEQ + ks0) * HDIM;
        uint32_t kbs = kbb + (uint32_t)st * 128 * SQ * 2;
        #pragma unroll
        for (int i = 0; i < 8; i++) {
            int ch = tid + i * 256; int rr = ch >> 4, c = (ch & 15) * 8;
            cp16(kbs + (uint32_t)(rr * SQ + c) * 2, kp + (size_t)rr * HDIM + c);
        }
        const __half* vp = v + ((size_t)b * SEQ + ks0) * HDIM;
        uint32_t vbs = vbb + (uint32_t)st * 128 * SQ * 2;
        #pragma unroll
        for (int i = 0; i < 8; i++) {
            int ch = tid + i * 256; int rr = ch >> 4, c = (ch & 15) * 8;
            cp16(vbs + (uint32_t)(rr * SQ + c) * 2, vp + (size_t)rr * HDIM + c);
        }
    };

    loadKV(0, 0);
    CP_COMMIT();

    uint32_t qaddr = qb + (uint32_t)((m0 + (lane & 15)) * SQ + (lane >> 4) * 8) * 2;
    uint32_t koff  = (uint32_t)(((lane >> 4) * 8 + (lane & 7)) * SQ +
                                ((lane >> 3) & 1) * 8) * 2;
    uint32_t voff  = (uint32_t)(((lane & 7) + ((lane >> 3) & 1) * 8) * SQ +
                                (lane >> 4) * 8) * 2;

    float m_0 = -1e30f, m_1 = -1e30f, l_0 = 0.f, l_1 = 0.f;
    float oacc[16][4];
    #pragma unroll
    for (int di = 0; di < 16; di++)
        #pragma unroll
        for (int j = 0; j < 4; j++) oacc[di][j] = 0.f;

    int nkt = qt + 1;
    for (int kt = 0; kt < nkt; kt++) {
        CP_WAIT(0);
        __syncthreads();
        if (kt + 1 < nkt) { loadKV((kt + 1) & 1, kt + 1); CP_COMMIT(); }
        uint32_t ka = kbb + (uint32_t)((kt & 1) * 128 * SQ) * 2 + koff;
        uint32_t va = vbb + (uint32_t)((kt & 1) * 128 * SQ) * 2 + voff;

        // S = Q K^T  (16 x 128 per warp)
        float sacc[16][4];
        #pragma unroll
        for (int ni = 0; ni < 16; ni++)
            #pragma unroll
            for (int j = 0; j < 4; j++) sacc[ni][j] = 0.f;

        #pragma unroll
        for (int kk = 0; kk < 128; kk += 16) {
            uint32_t af[4];
            LDSM4(af[0], af[1], af[2], af[3], qaddr + (uint32_t)(kk * 2));
            uint32_t bf[16][2];
            #pragma unroll
            for (int np = 0; np < 8; np++)
                LDSM4(bf[2*np][0], bf[2*np][1], bf[2*np+1][0], bf[2*np+1][1],
                      ka + (uint32_t)(kk * 2) + (uint32_t)(np * 16 * SQ * 2));
            #pragma unroll
            for (int ni = 0; ni < 16; ni++)
                mma_f16(sacc[ni], af, bf[ni]);
        }

        // causal mask: only the diagonal tile needs it
        if (kt == qt) {
            int ks0 = kt * 128;
            int row0 = qs0 + m0 + r, row1 = row0 + 8;
            #pragma unroll
            for (int ni = 0; ni < 16; ni++) {
                int c0 = ks0 + ni * 8 + cl * 2, c1 = c0 + 1;
                if (c0 > row0) sacc[ni][0] = -1e30f;
                if (c1 > row0) sacc[ni][1] = -1e30f;
                if (c0 > row1) sacc[ni][2] = -1e30f;
                if (c1 > row1) sacc[ni][3] = -1e30f;
            }
        }

        // online softmax (base 2)
        float mx0 = -1e30f, mx1 = -1e30f;
        #pragma unroll
        for (int ni = 0; ni < 16; ni++) {
            mx0 = fmaxf(mx0, fmaxf(sacc[ni][0], sacc[ni][1]));
            mx1 = fmaxf(mx1, fmaxf(sacc[ni][2], sacc[ni][3]));
        }
        mx0 = fmaxf(mx0, __shfl_xor_sync(0xffffffffu, mx0, 1));
        mx0 = fmaxf(mx0, __shfl_xor_sync(0xffffffffu, mx0, 2));
        mx1 = fmaxf(mx1, __shfl_xor_sync(0xffffffffu, mx1, 1));
        mx1 = fmaxf(mx1, __shfl_xor_sync(0xffffffffu, mx1, 2));
        float mn0 = fmaxf(m_0, mx0), mn1 = fmaxf(m_1, mx1);
        float a0 = ex2(m_0 - mn0), a1 = ex2(m_1 - mn1);
        float s0 = 0.f, s1 = 0.f;
        #pragma unroll
        for (int ni = 0; ni < 16; ni++) {
            sacc[ni][0] = ex2(sacc[ni][0] - mn0);
            sacc[ni][1] = ex2(sacc[ni][1] - mn0);
            sacc[ni][2] = ex2(sacc[ni][2] - mn1);
            sacc[ni][3] = ex2(sacc[ni][3] - mn1);
            s0 += sacc[ni][0] + sacc[ni][1];
            s1 += sacc[ni][2] + sacc[ni][3];
        }
        s0 += __shfl_xor_sync(0xffffffffu, s0, 1);
        s0 += __shfl_xor_sync(0xffffffffu, s0, 2);
        s1 += __shfl_xor_sync(0xffffffffu, s1, 1);
        s1 += __shfl_xor_sync(0xffffffffu, s1, 2);
        l_0 = l_0 * a0 + s0; l_1 = l_1 * a1 + s1;
        m_0 = mn0; m_1 = mn1;
        #pragma unroll
        for (int di = 0; di < 16; di++) {
            oacc[di][0] *= a0; oacc[di][1] *= a0;
            oacc[di][2] *= a1; oacc[di][3] *= a1;
        }

        // P fragments (registers -> A-frag)
        uint32_t pa[8][4];
        #pragma unroll
        for (int j = 0; j < 8; j++) {
            pa[j][0] = packh2(sacc[2*j  ][0], sacc[2*j  ][1]);
            pa[j][1] = packh2(sacc[2*j  ][2], sacc[2*j  ][3]);
            pa[j][2] = packh2(sacc[2*j+1][0], sacc[2*j+1][1]);
            pa[j][3] = packh2(sacc[2*j+1][2], sacc[2*j+1][3]);
        }

        // O += P V   (V [s][d] via ldmatrix.trans)
        #pragma unroll
        for (int j = 0; j < 8; j++) {
            #pragma unroll
            for (int dp = 0; dp < 8; dp++) {
                uint32_t bf[4];
                LDSM4T(bf[0], bf[1], bf[2], bf[3],
                       va + (uint32_t)(j * 16 * SQ * 2) + (uint32_t)(dp * 16 * 2));
                mma_f16(oacc[2*dp    ], pa[j], bf    );
                mma_f16(oacc[2*dp + 1], pa[j], bf + 2);
            }
        }
    }

    // epilogue
    float i0 = 1.f / l_0, i1 = 1.f / l_1;
    __half* op = o + ((size_t)(b * SEQ + qs0 + m0) * NHEAD + h) * HDIM;
    #pragma unroll
    for (int di = 0; di < 16; di++) {
        int c = di * 8 + cl * 2;
        *(__half2*)&op[(size_t)r * (NHEAD * HDIM) + c] =
            __floats2half2_rn(oacc[di][0] * i0, oacc[di][1] * i0);
        *(__half2*)&op[(size_t)(r + 8) * (NHEAD * HDIM) + c] =
            __floats2half2_rn(oacc[di][2] * i1, oacc[di][3] * i1);
    }
}

// ---------------- launch ----------------
extern "C" void kernel_launch(void* const* d_in, const int* in_sizes, int n_in,
                              void* d_out, int out_size)
{
    const float* x     = (const float*)d_in[0];
    const float* wq    = (const float*)d_in[2];
    const float* wq_b  = (const float*)d_in[3];
    const float* wk    = (const float*)d_in[4];
    const float* wk_b  = (const float*)d_in[5];
    const float* wv    = (const float*)d_in[6];
    const float* wv_b  = (const float*)d_in[7];
    const float* wo    = (const float*)d_in[8];
    const float* wo_b  = (const float*)d_in[9];
    const float* w1    = (const float*)d_in[10];
    const float* w1_b  = (const float*)d_in[11];
    const float* w2    = (const float*)d_in[12];
    const float* w2_b  = (const float*)d_in[13];
    const float* ln1_s = (const float*)d_in[14];
    const float* ln1_b = (const float*)d_in[15];
    const float* ln2_s = (const float*)d_in[16];
    const float* ln2_b = (const float*)d_in[17];
    float* out = (float*)d_out;

    __half *hh, *qh, *kh, *vh, *oh, *ffh;
    __half *cwqkv, *cwo, *cw1, *cw2;
    float  *x1, *bqkv;
    cudaGetSymbolAddress((void**)&hh,    g_hh);
    cudaGetSymbolAddress((void**)&qh,    g_qh);
    cudaGetSymbolAddress((void**)&kh,    g_kh);
    cudaGetSymbolAddress((void**)&vh,    g_vh);
    cudaGetSymbolAddress((void**)&oh,    g_oh);
    cudaGetSymbolAddress((void**)&x1,    g_x1);
    cudaGetSymbolAddress((void**)&ffh,   g_ffh);
    cudaGetSymbolAddress((void**)&cwqkv, g_wqkv);
    cudaGetSymbolAddress((void**)&bqkv,  g_bqkv);
    cudaGetSymbolAddress((void**)&cwo,   g_wo);
    cudaGetSymbolAddress((void**)&cw1,   g_w1);
    cudaGetSymbolAddress((void**)&cw2,   g_w2);

    cudaFuncSetAttribute(fattn, cudaFuncAttributeMaxDynamicSharedMemorySize, FA_SMEM);
    cudaFuncSetAttribute(hgemm<1>, cudaFuncAttributeMaxDynamicSharedMemorySize, SMEM_H);
    cudaFuncSetAttribute(hgemm<2>, cudaFuncAttributeMaxDynamicSharedMemorySize, SMEM_H);
    cudaFuncSetAttribute(hgemm_qkv, cudaFuncAttributeMaxDynamicSharedMemorySize, SMEM_H);

    // Q pre-scale folds softmax scale AND log2(e) for base-2 softmax
    const float qscale = 0.08838834764831845f * 1.44269504088896340f;

    // 1: all prep (weight cvt + bias concat + LN1) in one launch
    prep_all<<<45577, 256>>>(wq, wk, wv, wo, w1, w2, wq_b, wk_b, wv_b,
                             x, ln1_s, ln1_b, cwqkv, cwo, cw1, cw2, bqkv, hh);
    // 2: fused QKV projection
    hgemm_qkv<<<dim3(NQKV/GBN, MTOK/128), 256, SMEM_H>>>(
        hh, cwqkv, bqkv, qh, kh, vh, DMODEL, qscale);
    // 3: attention (half out, V untransposed)
    fattn<<<dim3(SEQ/128, 2*NHEAD), 256, FA_SMEM>>>(qh, kh, vh, oh);
    // 4: x1 = x + O @ wo + wo_b  (float out)
    hgemm<1><<<dim3(DMODEL/GBN, MTOK/128), 256, SMEM_H>>>(
        oh, cwo, wo_b, x, x1, MTOK, DMODEL, DMODEL);
    // 5: h = LN2(x1) (half)
    ln_kernel<<<MTOK, 256>>>(x1, ln2_s, ln2_b, hh);
    // 6: ff = gelu(h @ w1 + w1_b)  (half out)
    hgemm<2><<<dim3(FFDIM/GBN, MTOK/128), 256, SMEM_H>>>(
        hh, cw1, w1_b, nullptr, ffh, MTOK, FFDIM, DMODEL);
    // 7: out = x1 + ff @ w2 + w2_b (float out)
    hgemm<1><<<dim3(DMODEL/GBN, MTOK/128), 256, SMEM_H>>>(
        ffh, cw2, w2_b, x1, out, MTOK, DMODEL, FFDIM);
}